// round 14
// baseline (speedup 1.0000x reference)
#include <cuda_runtime.h>
#include <cstdint>

// LIF recurrence: T=64 steps, B*N = 524288 independent lanes.
//   h = v + (x - v) * 0.5 ; s = (h>=1) ; v = s ? 0 : h
// Pure HBM stream: 134 MB in + 134 MB out (compulsory, zero reuse).
//
// R13 found the band wasn't a wall: clean unroll 4->8 cut harness
// 47.4 -> 45.8us (lower loop overhead per byte -> better sustained
// clock residency; ncu one-shot unchanged at ~37us).
// R14: follow the gradient — unroll 16. Body ~5KB, still fits the
// ~6KB L0 I$; halves remaining loop-counter/branch overhead again.
// Everything else identical to the proven R6/R13 structure: float4,
// distance-1 scalar prefetch, plain LDG.128/STG.128, 128-thr blocks
// (1024 CTAs, single wave, even per-SM balance).

static constexpr int T = 64;

__global__ void __launch_bounds__(128) lif_kernel(const float4* __restrict__ x,
                                                  float4* __restrict__ out,
                                                  int lanes4)  // B*N/4 per timestep
{
    int i = blockIdx.x * blockDim.x + threadIdx.x;
    if (i >= lanes4) return;

    float4 v = make_float4(0.f, 0.f, 0.f, 0.f);

    // distance-1 scalar prefetch
    float4 xt = x[i];

    #pragma unroll 16
    for (int t = 0; t < T; ++t) {
        float4 xnext;
        if (t + 1 < T) xnext = x[(size_t)(t + 1) * lanes4 + i];

        float4 h, s;
        h.x = v.x + (xt.x - v.x) * 0.5f;
        h.y = v.y + (xt.y - v.y) * 0.5f;
        h.z = v.z + (xt.z - v.z) * 0.5f;
        h.w = v.w + (xt.w - v.w) * 0.5f;

        s.x = (h.x >= 1.0f) ? 1.0f : 0.0f;
        s.y = (h.y >= 1.0f) ? 1.0f : 0.0f;
        s.z = (h.z >= 1.0f) ? 1.0f : 0.0f;
        s.w = (h.w >= 1.0f) ? 1.0f : 0.0f;

        v.x = (h.x >= 1.0f) ? 0.0f : h.x;
        v.y = (h.y >= 1.0f) ? 0.0f : h.y;
        v.z = (h.z >= 1.0f) ? 0.0f : h.z;
        v.w = (h.w >= 1.0f) ? 0.0f : h.w;

        out[(size_t)t * lanes4 + i] = s;

        xt = xnext;
    }
}

extern "C" void kernel_launch(void* const* d_in, const int* in_sizes, int n_in,
                              void* d_out, int out_size)
{
    const float4* x = (const float4*)d_in[0];
    float4* out = (float4*)d_out;

    int total = in_sizes[0];          // T * B * N
    int lanes = total / T;            // 524288
    int lanes4 = lanes / 4;           // 131072

    int threads = 128;                // 1024 CTAs -> single wave, even balance
    int blocks = (lanes4 + threads - 1) / threads;
    lif_kernel<<<blocks, threads>>>(x, out, lanes4);
}

// round 15
// speedup vs baseline: 1.0367x; 1.0367x over previous
#include <cuda_runtime.h>
#include <cstdint>

// LIF recurrence: T=64 steps, B*N = 524288 independent lanes.
//   h = v + (x - v) * 0.5 ; s = (h>=1) ; v = s ? 0 : h
// Pure HBM stream: 134 MB in + 134 MB out (compulsory, zero reuse).
//
// R15 = exact replication of R13 (unroll 8, best harness 45.8us) to
// test whether that number was real or a timer outlier: R13's ncu
// profile (37.15us / 72.9% DRAM) was identical to R12/R14, so the
// harness delta never appeared in the profile. Unroll 16 (R14)
// regressed to 47.9, bracketing unroll 8 as the candidate optimum.
// Structure: float4, distance-1 scalar prefetch, plain LDG.128/
// STG.128, 128-thread blocks (1024 CTAs, single wave, even balance).

static constexpr int T = 64;

__global__ void __launch_bounds__(128) lif_kernel(const float4* __restrict__ x,
                                                  float4* __restrict__ out,
                                                  int lanes4)  // B*N/4 per timestep
{
    int i = blockIdx.x * blockDim.x + threadIdx.x;
    if (i >= lanes4) return;

    float4 v = make_float4(0.f, 0.f, 0.f, 0.f);

    // distance-1 scalar prefetch
    float4 xt = x[i];

    #pragma unroll 8
    for (int t = 0; t < T; ++t) {
        float4 xnext;
        if (t + 1 < T) xnext = x[(size_t)(t + 1) * lanes4 + i];

        float4 h, s;
        h.x = v.x + (xt.x - v.x) * 0.5f;
        h.y = v.y + (xt.y - v.y) * 0.5f;
        h.z = v.z + (xt.z - v.z) * 0.5f;
        h.w = v.w + (xt.w - v.w) * 0.5f;

        s.x = (h.x >= 1.0f) ? 1.0f : 0.0f;
        s.y = (h.y >= 1.0f) ? 1.0f : 0.0f;
        s.z = (h.z >= 1.0f) ? 1.0f : 0.0f;
        s.w = (h.w >= 1.0f) ? 1.0f : 0.0f;

        v.x = (h.x >= 1.0f) ? 0.0f : h.x;
        v.y = (h.y >= 1.0f) ? 0.0f : h.y;
        v.z = (h.z >= 1.0f) ? 0.0f : h.z;
        v.w = (h.w >= 1.0f) ? 0.0f : h.w;

        out[(size_t)t * lanes4 + i] = s;

        xt = xnext;
    }
}

extern "C" void kernel_launch(void* const* d_in, const int* in_sizes, int n_in,
                              void* d_out, int out_size)
{
    const float4* x = (const float4*)d_in[0];
    float4* out = (float4*)d_out;

    int total = in_sizes[0];          // T * B * N
    int lanes = total / T;            // 524288
    int lanes4 = lanes / 4;           // 131072

    int threads = 128;                // 1024 CTAs -> single wave, even balance
    int blocks = (lanes4 + threads - 1) / threads;
    lif_kernel<<<blocks, threads>>>(x, out, lanes4);
}